// round 1
// baseline (speedup 1.0000x reference)
#include <cuda_runtime.h>
#include <math.h>
#include <stdint.h>

// Problem dims (fixed by the dataset generator)
#define B_  1024
#define F_  4096
#define V_  20000
#define E_  512
#define H_  1024
#define L_  20
#define D_  4
#define G4H 4096   // 4*H

// ---------------- scratch (no allocations allowed) ----------------
__device__ float g_h[B_*H_];
__device__ float g_c[B_*H_];
__device__ float g_gates[(size_t)B_*G4H];
__device__ float g_w[B_*E_];
__device__ float g_logits[(size_t)B_*V_];
__device__ int   g_msg[L_*B_];
__device__ float g_logprob[B_];
__device__ float g_bias_s[G4H];
__device__ float g_bias_r[G4H];
__device__ float g_r[(size_t)B_*F_];
__device__ float g_ts[(size_t)B_*B_];
__device__ float g_ds[(size_t)D_*B_*B_];
__device__ float g_lsum[B_];
__device__ float g_tp[B_];
__device__ float g_dp[D_*B_];

// ---------------- GEMM: C[M,N] (+)= A[M,K] @ B[N,K]^T (+ bias[N]) ----------------
// A row-major [M,K], Bm row-major [N,K] (both K-contiguous -> "NT" gemm).
// M must be a multiple of 128 (always 1024 here). N may have a tail. K % 16 == 0.
#define BM 128
#define BN 128
#define BKK 16

template<bool ACC, bool BIAS>
__global__ __launch_bounds__(256, 2)
void gemm_nt(const float* __restrict__ A, const float* __restrict__ Bm,
             const float* __restrict__ bias, float* __restrict__ C,
             int M, int N, int K)
{
    __shared__ float As[BKK][BM + 4];
    __shared__ float Bs[BKK][BN + 4];

    const int tid = threadIdx.x;
    const int tx = tid & 15;       // 0..15  -> N direction
    const int ty = tid >> 4;       // 0..15  -> M direction
    const int bm = blockIdx.y * BM;
    const int bn = blockIdx.x * BN;

    const int lrow = tid >> 2;         // 0..63
    const int lk4  = (tid & 3) * 4;    // 0,4,8,12

    float acc[8][8];
#pragma unroll
    for (int i = 0; i < 8; i++)
#pragma unroll
        for (int j = 0; j < 8; j++) acc[i][j] = 0.0f;

    for (int kt = 0; kt < K; kt += BKK) {
        // load A tile (M always in range)
#pragma unroll
        for (int r = 0; r < 2; r++) {
            int row = lrow + r * 64;
            float4 v = *(const float4*)&A[(size_t)(bm + row) * K + kt + lk4];
            As[lk4 + 0][row] = v.x; As[lk4 + 1][row] = v.y;
            As[lk4 + 2][row] = v.z; As[lk4 + 3][row] = v.w;
        }
        // load B tile (guard N tail)
#pragma unroll
        for (int r = 0; r < 2; r++) {
            int row = lrow + r * 64;
            int nrow = bn + row;
            float4 v = make_float4(0.f, 0.f, 0.f, 0.f);
            if (nrow < N) v = *(const float4*)&Bm[(size_t)nrow * K + kt + lk4];
            Bs[lk4 + 0][row] = v.x; Bs[lk4 + 1][row] = v.y;
            Bs[lk4 + 2][row] = v.z; Bs[lk4 + 3][row] = v.w;
        }
        __syncthreads();

#pragma unroll
        for (int k = 0; k < BKK; k++) {
            float a[8], b[8];
            *(float4*)&a[0] = *(const float4*)&As[k][ty * 8];
            *(float4*)&a[4] = *(const float4*)&As[k][ty * 8 + 4];
            *(float4*)&b[0] = *(const float4*)&Bs[k][tx * 8];
            *(float4*)&b[4] = *(const float4*)&Bs[k][tx * 8 + 4];
#pragma unroll
            for (int i = 0; i < 8; i++)
#pragma unroll
                for (int j = 0; j < 8; j++)
                    acc[i][j] = fmaf(a[i], b[j], acc[i][j]);
        }
        __syncthreads();
    }

    // epilogue
#pragma unroll
    for (int i = 0; i < 8; i++) {
        int m = bm + ty * 8 + i;
#pragma unroll
        for (int j = 0; j < 8; j++) {
            int n = bn + tx * 8 + j;
            if (n < N) {
                float v = acc[i][j];
                if (BIAS) v += bias[n];
                size_t off = (size_t)m * N + n;
                if (ACC) v += C[off];
                C[off] = v;
            }
        }
    }
}

// ---------------- small kernels ----------------
__global__ void zero_kernel(float* p, int n) {
    int i = blockIdx.x * blockDim.x + threadIdx.x;
    if (i < n) p[i] = 0.0f;
}

__global__ void add_vec(const float* a, const float* b, float* o, int n) {
    int i = blockIdx.x * blockDim.x + threadIdx.x;
    if (i < n) o[i] = a[i] + b[i];
}

// broadcast emb[*startp] to all rows
__global__ void gather_start(const float* __restrict__ emb, const int* __restrict__ startp,
                             float* __restrict__ out) {
    int s = *startp;
    int b = blockIdx.x;
    int e = threadIdx.x;  // 128 threads, E_/4 = 128 float4
    ((float4*)out)[(size_t)b * (E_ / 4) + e] =
        ((const float4*)emb)[(size_t)s * (E_ / 4) + e];
}

__global__ void gather_tok(const float* __restrict__ emb, const int* __restrict__ tok,
                           float* __restrict__ out) {
    int b = blockIdx.x;
    int t = tok[b];
    int e = threadIdx.x;
    ((float4*)out)[(size_t)b * (E_ / 4) + e] =
        ((const float4*)emb)[(size_t)t * (E_ / 4) + e];
}

__device__ __forceinline__ float sigf(float x) { return 1.0f / (1.0f + expf(-x)); }

// gates layout [B, 4H] chunks: i, f, g, o
__global__ void lstm_cell(const float* __restrict__ gates,
                          float* __restrict__ h, float* __restrict__ c) {
    int idx = blockIdx.x * blockDim.x + threadIdx.x;
    if (idx >= B_ * H_) return;
    int b = idx >> 10;            // /H_
    int j = idx & (H_ - 1);
    size_t base = (size_t)b * G4H;
    float gi = gates[base + j];
    float gf = gates[base + H_ + j];
    float gg = gates[base + 2 * H_ + j];
    float go = gates[base + 3 * H_ + j];
    float cn = sigf(gf) * c[idx] + sigf(gi) * tanhf(gg);
    c[idx] = cn;
    h[idx] = sigf(go) * tanhf(cn);
}

// per-row argmax over V (lowest index on ties = JAX semantics);
// if writeLp: logprob[b] = logits[amax] - logsumexp = -log(sum exp(x - max))
__global__ void argmax_row(const float* __restrict__ logits, int* __restrict__ msg,
                           float* __restrict__ logprob, int writeLp) {
    int b = blockIdx.x;
    const float* row = logits + (size_t)b * V_;
    int tid = threadIdx.x;

    float best = -3.4e38f;
    int bi = 0x7fffffff;
    for (int v = tid; v < V_; v += 256) {
        float x = row[v];
        if (x > best) { best = x; bi = v; }
    }
    __shared__ float sv[256];
    __shared__ int   si[256];
    sv[tid] = best; si[tid] = bi;
    __syncthreads();
    for (int s = 128; s > 0; s >>= 1) {
        if (tid < s) {
            if (sv[tid + s] > sv[tid] ||
                (sv[tid + s] == sv[tid] && si[tid + s] < si[tid])) {
                sv[tid] = sv[tid + s]; si[tid] = si[tid + s];
            }
        }
        __syncthreads();
    }
    float m = sv[0];
    int amax = si[0];
    if (tid == 0) msg[b] = amax;

    if (writeLp) {
        __syncthreads();
        float s = 0.0f;
        for (int v = tid; v < V_; v += 256) s += expf(row[v] - m);
        sv[tid] = s;
        __syncthreads();
        for (int st = 128; st > 0; st >>= 1) {
            if (tid < st) sv[tid] += sv[tid + st];
            __syncthreads();
        }
        if (tid == 0) logprob[b] = -logf(sv[0]);
    }
}

// per-row-b reductions over k: hinge*logprob sum, exp(ts) sum, exp(ds[d]) sums
__global__ void reduce_rows(const float* __restrict__ ts, const float* __restrict__ ds,
                            const float* __restrict__ lp,
                            float* __restrict__ lsum, float* __restrict__ tp,
                            float* __restrict__ dp) {
    int b = blockIdx.x;
    int tid = threadIdx.x;
    float l = 0.f, t = 0.f, d0 = 0.f, d1 = 0.f, d2 = 0.f, d3 = 0.f;
    for (int k = tid; k < B_; k += 256) {
        float tv = ts[(size_t)b * B_ + k];
        float v0 = ds[(size_t)0 * B_ * B_ + (size_t)b * B_ + k];
        float v1 = ds[(size_t)1 * B_ * B_ + (size_t)b * B_ + k];
        float v2 = ds[(size_t)2 * B_ * B_ + (size_t)b * B_ + k];
        float v3 = ds[(size_t)3 * B_ * B_ + (size_t)b * B_ + k];
        float h = fmaxf(0.f, 1.f - tv + v0) + fmaxf(0.f, 1.f - tv + v1)
                + fmaxf(0.f, 1.f - tv + v2) + fmaxf(0.f, 1.f - tv + v3);
        l += h * lp[k];
        t += expf(tv);
        d0 += expf(v0); d1 += expf(v1); d2 += expf(v2); d3 += expf(v3);
    }
    __shared__ float sh[6][256];
    sh[0][tid] = l; sh[1][tid] = t; sh[2][tid] = d0;
    sh[3][tid] = d1; sh[4][tid] = d2; sh[5][tid] = d3;
    __syncthreads();
    for (int s = 128; s > 0; s >>= 1) {
        if (tid < s)
            for (int q = 0; q < 6; q++) sh[q][tid] += sh[q][tid + s];
        __syncthreads();
    }
    if (tid == 0) {
        lsum[b] = sh[0][0];
        tp[b] = sh[1][0];
        dp[0 * B_ + b] = sh[2][0];
        dp[1 * B_ + b] = sh[3][0];
        dp[2 * B_ + b] = sh[4][0];
        dp[3 * B_ + b] = sh[5][0];
    }
}

__global__ void finalize(const float* __restrict__ lsum, const float* __restrict__ tp,
                         const float* __restrict__ dp, float* __restrict__ out) {
    int tid = threadIdx.x;
    float lo = 0.f, an = 0.f;
    for (int b = tid; b < B_; b += 256) {
        lo += lsum[b];
        float t = tp[b];
        bool ok = (t >= dp[0 * B_ + b]) && (t >= dp[1 * B_ + b]) &&
                  (t >= dp[2 * B_ + b]) && (t >= dp[3 * B_ + b]);
        an += ok ? 1.0f : 0.0f;
    }
    __shared__ float s0[256], s1[256];
    s0[tid] = lo; s1[tid] = an;
    __syncthreads();
    for (int s = 128; s > 0; s >>= 1) {
        if (tid < s) { s0[tid] += s0[tid + s]; s1[tid] += s1[tid + s]; }
        __syncthreads();
    }
    if (tid == 0) {
        out[0] = -s0[0] / ((float)B_ * (float)B_);
        out[1] = s1[0] / (float)B_;
    }
}

// ---------------- host orchestration ----------------
static inline dim3 gemm_grid(int M, int N) {
    return dim3((N + BN - 1) / BN, M / BM);
}

extern "C" void kernel_launch(void* const* d_in, const int* in_sizes, int n_in,
                              void* d_out, int out_size) {
    (void)in_sizes; (void)n_in; (void)out_size;
    const float* target      = (const float*)d_in[0];   // [B,F]
    const float* distractors = (const float*)d_in[1];   // [D,B,F]
    const int*   start_tok   = (const int*)d_in[2];
    // d_in[3] = max_sentence_length (compile-time L_=20)
    const float* emb_s   = (const float*)d_in[4];       // [V,E]
    const float* Wih_s   = (const float*)d_in[5];       // [4H,E]
    const float* Whh_s   = (const float*)d_in[6];       // [4H,H]
    const float* bih_s   = (const float*)d_in[7];
    const float* bhh_s   = (const float*)d_in[8];
    const float* aff_s_W = (const float*)d_in[9];       // [H,F]
    const float* aff_s_b = (const float*)d_in[10];      // [H]
    const float* probs_W = (const float*)d_in[11];      // [V,H]
    const float* probs_b = (const float*)d_in[12];      // [V]
    const float* emb_r   = (const float*)d_in[13];
    const float* Wih_r   = (const float*)d_in[14];
    const float* Whh_r   = (const float*)d_in[15];
    const float* bih_r   = (const float*)d_in[16];
    const float* bhh_r   = (const float*)d_in[17];
    const float* aff_r_W = (const float*)d_in[18];      // [F,H]
    const float* aff_r_b = (const float*)d_in[19];      // [F]
    float* out = (float*)d_out;

    // resolve scratch symbol addresses
    float *p_h, *p_c, *p_gates, *p_w, *p_logits, *p_logprob, *p_bias_s, *p_bias_r;
    float *p_r, *p_ts, *p_ds, *p_lsum, *p_tp, *p_dp;
    int *p_msg;
    cudaGetSymbolAddress((void**)&p_h, g_h);
    cudaGetSymbolAddress((void**)&p_c, g_c);
    cudaGetSymbolAddress((void**)&p_gates, g_gates);
    cudaGetSymbolAddress((void**)&p_w, g_w);
    cudaGetSymbolAddress((void**)&p_logits, g_logits);
    cudaGetSymbolAddress((void**)&p_msg, g_msg);
    cudaGetSymbolAddress((void**)&p_logprob, g_logprob);
    cudaGetSymbolAddress((void**)&p_bias_s, g_bias_s);
    cudaGetSymbolAddress((void**)&p_bias_r, g_bias_r);
    cudaGetSymbolAddress((void**)&p_r, g_r);
    cudaGetSymbolAddress((void**)&p_ts, g_ts);
    cudaGetSymbolAddress((void**)&p_ds, g_ds);
    cudaGetSymbolAddress((void**)&p_lsum, g_lsum);
    cudaGetSymbolAddress((void**)&p_tp, g_tp);
    cudaGetSymbolAddress((void**)&p_dp, g_dp);

    // combined LSTM biases
    add_vec<<<(G4H + 255) / 256, 256>>>(bih_s, bhh_s, p_bias_s, G4H);
    add_vec<<<(G4H + 255) / 256, 256>>>(bih_r, bhh_r, p_bias_r, G4H);

    // ---- Sender ----
    // h0 = target @ aff_s_W^T + aff_s_b ; c0 = 0
    gemm_nt<false, true><<<gemm_grid(B_, H_), 256>>>(target, aff_s_W, aff_s_b, p_h, B_, H_, F_);
    zero_kernel<<<(B_ * H_ + 255) / 256, 256>>>(p_c, B_ * H_);

    for (int s = 0; s < L_; s++) {
        if (s == 0) gather_start<<<B_, 128>>>(emb_s, start_tok, p_w);
        else        gather_tok<<<B_, 128>>>(emb_s, p_msg + (s - 1) * B_, p_w);

        gemm_nt<false, true><<<gemm_grid(B_, G4H), 256>>>(p_w, Wih_s, p_bias_s, p_gates, B_, G4H, E_);
        gemm_nt<true,  false><<<gemm_grid(B_, G4H), 256>>>(p_h, Whh_s, nullptr, p_gates, B_, G4H, H_);
        lstm_cell<<<(B_ * H_ + 255) / 256, 256>>>(p_gates, p_h, p_c);

        gemm_nt<false, true><<<gemm_grid(B_, V_), 256>>>(p_h, probs_W, probs_b, p_logits, B_, V_, H_);
        argmax_row<<<B_, 256>>>(p_logits, p_msg + s * B_, p_logprob, (s == L_ - 1) ? 1 : 0);
    }

    // ---- Receiver ----
    zero_kernel<<<(B_ * H_ + 255) / 256, 256>>>(p_h, B_ * H_);
    zero_kernel<<<(B_ * H_ + 255) / 256, 256>>>(p_c, B_ * H_);
    for (int s = 0; s < L_; s++) {
        gather_tok<<<B_, 128>>>(emb_r, p_msg + s * B_, p_w);
        gemm_nt<false, true><<<gemm_grid(B_, G4H), 256>>>(p_w, Wih_r, p_bias_r, p_gates, B_, G4H, E_);
        gemm_nt<true,  false><<<gemm_grid(B_, G4H), 256>>>(p_h, Whh_r, nullptr, p_gates, B_, G4H, H_);
        lstm_cell<<<(B_ * H_ + 255) / 256, 256>>>(p_gates, p_h, p_c);
    }

    // r = hr @ aff_r_W^T + aff_r_b
    gemm_nt<false, true><<<gemm_grid(B_, F_), 256>>>(p_h, aff_r_W, aff_r_b, p_r, B_, F_, H_);

    // ts = target @ r^T ; ds[d] = distractors[d] @ r^T
    gemm_nt<false, false><<<gemm_grid(B_, B_), 256>>>(target, p_r, nullptr, p_ts, B_, B_, F_);
    for (int d = 0; d < D_; d++)
        gemm_nt<false, false><<<gemm_grid(B_, B_), 256>>>(
            distractors + (size_t)d * B_ * F_, p_r, nullptr,
            p_ds + (size_t)d * B_ * B_, B_, B_, F_);

    // loss + accuracy
    reduce_rows<<<B_, 256>>>(p_ts, p_ds, p_logprob, p_lsum, p_tp, p_dp);
    finalize<<<1, 256>>>(p_lsum, p_tp, p_dp, out);
}